// round 10
// baseline (speedup 1.0000x reference)
#include <cuda_runtime.h>
#include <cuda_fp16.h>
#include <math.h>
#include <stdint.h>

#define TT   8192
#define EE   1024
#define HH   16
#define DD   64
#define NSEG 8
#define LL   1024

// Scratch (device globals — no allocation allowed in kernel_launch)
__device__ __half g_hh [TT * EE];       // hs in half
__device__ __half g_wh [4 * EE * EE];   // 4 weights in half
__device__ __half g_qh [TT * EE];       // Q projection (half)
__device__ __half g_kh [TT * EE];       // K projection (half)
__device__ __half g_vth[EE * TT];       // V projection, transposed [e][token]
__device__ __half g_oh [TT * EE];       // attention output (half)

// ---------------------------------------------------------------------------
// helpers
// ---------------------------------------------------------------------------
__device__ __forceinline__ void ldsm4(uint32_t* r, uint32_t addr) {
    asm volatile("ldmatrix.sync.aligned.m8n8.x4.shared.b16 {%0,%1,%2,%3}, [%4];"
                 : "=r"(r[0]), "=r"(r[1]), "=r"(r[2]), "=r"(r[3]) : "r"(addr));
}
__device__ __forceinline__ void mma16(float* c, const uint32_t* a, uint32_t b0, uint32_t b1) {
    asm volatile("mma.sync.aligned.m16n8k16.row.col.f32.f16.f16.f32 "
                 "{%0,%1,%2,%3}, {%4,%5,%6,%7}, {%8,%9}, {%0,%1,%2,%3};"
                 : "+f"(c[0]), "+f"(c[1]), "+f"(c[2]), "+f"(c[3])
                 : "r"(a[0]), "r"(a[1]), "r"(a[2]), "r"(a[3]), "r"(b0), "r"(b1));
}
__device__ __forceinline__ void cp_async16(uint32_t dst, const void* src) {
    asm volatile("cp.async.cg.shared.global [%0], [%1], 16;\n" :: "r"(dst), "l"(src));
}
__device__ __forceinline__ void cp_commit() { asm volatile("cp.async.commit_group;\n"); }
template <int N> __device__ __forceinline__ void cp_wait() {
    asm volatile("cp.async.wait_group %0;\n" :: "n"(N));
}

// ---------------------------------------------------------------------------
// fused float -> half conversion
// ---------------------------------------------------------------------------
__global__ void f2h_all(const float* __restrict__ hs,
                        const float* __restrict__ w0, const float* __restrict__ w1,
                        const float* __restrict__ w2, const float* __restrict__ w3,
                        __half* __restrict__ hh, __half* __restrict__ wh)
{
    const int nAct4 = TT * EE / 4;
    const int nW4   = EE * EE / 4;
    int i = blockIdx.x * blockDim.x + threadIdx.x;

    const float* src; __half* dst; int j;
    if (i < nAct4) { src = hs; dst = hh; j = i; }
    else {
        int t = i - nAct4;
        int w = t / nW4;
        j = t - w * nW4;
        src = (w == 0) ? w0 : (w == 1) ? w1 : (w == 2) ? w2 : w3;
        dst = wh + (size_t)w * EE * EE;
    }
    float4 v = ((const float4*)src)[j];
    __half2* o = (__half2*)dst;
    o[2 * j]     = __floats2half2_rn(v.x, v.y);
    o[2 * j + 1] = __floats2half2_rn(v.z, v.w);
}

// ---------------------------------------------------------------------------
// FP16 mma.sync GEMM core: 128x128 tile, BK=32, 6-stage cp.async,
// ONE barrier per slab, FULL-SLAB fragment preload (software-pipelined).
// 8 warps (2x4), warp 64x32, 1 CTA/SM (smem 120KB).
// ---------------------------------------------------------------------------
#define GH      40
#define ABY     (128 * GH * 2)            // 10240
#define STGB    (2 * ABY)                 // 20480
#define NSTAGE  6
#define NSLAB   (EE / 32)                 // 32

__device__ __forceinline__ void frag_offsets(int warp, int lane, uint32_t* aoff, uint32_t* boff)
{
    const int mW = (warp >> 2) * 64;
    const int nW = (warp & 3) * 32;
#pragma unroll
    for (int mi = 0; mi < 4; mi++)
        aoff[mi] = (uint32_t)(((mW + mi * 16 + (lane & 15)) * GH + ((lane >> 4) << 3)) << 1);
#pragma unroll
    for (int np = 0; np < 2; np++)
        boff[np] = (uint32_t)(((nW + np * 16 + (lane & 7) + ((lane >> 4) << 3)) * GH
                               + (((lane >> 3) & 1) << 3)) << 1) + ABY;
}

__device__ __forceinline__ void gemm_core(
    const __half* __restrict__ A, const __half* __restrict__ B, float c[4][4][4],
    uint32_t smemBase, int tid, int rowBase, int colBase,
    const uint32_t* aoff, const uint32_t* boff)
{
    const int lr = tid >> 1;
    const int lc = (tid & 1) * 8;
    const __half* Aptr = A + (size_t)(rowBase + lr) * EE + lc;
    const __half* Bptr = B + (size_t)(colBase + lr) * EE + lc;
    const uint32_t sA = smemBase + (uint32_t)((lr * GH + lc) * 2);
    const uint32_t sB = sA + ABY;

    // prologue: stages 0..NSTAGE-2
#pragma unroll
    for (int st = 0; st < NSTAGE - 1; st++) {
        const uint32_t bb = st * STGB;
        const int k0 = st * 32;
        cp_async16(sA + bb,      Aptr + k0);
        cp_async16(sA + bb + 32, Aptr + k0 + 16);
        cp_async16(sB + bb,      Bptr + k0);
        cp_async16(sB + bb + 32, Bptr + k0 + 16);
        cp_commit();
    }

    for (int s = 0; s < NSLAB; s++) {
        cp_wait<NSTAGE - 2>();     // slab s resident
        __syncthreads();           // all warps done reading buffer being refilled

        const int sn = s + NSTAGE - 1;
        if (sn < NSLAB) {
            const uint32_t nb = (uint32_t)(sn % NSTAGE) * STGB;
            const int k0 = sn * 32;
            cp_async16(sA + nb,      Aptr + k0);
            cp_async16(sA + nb + 32, Aptr + k0 + 16);
            cp_async16(sB + nb,      Bptr + k0);
            cp_async16(sB + nb + 32, Bptr + k0 + 16);
        }
        cp_commit();

        const uint32_t bb = (uint32_t)(s % NSTAGE) * STGB;

        // full-slab fragment preload (both k16 halves), then all 32 MMAs —
        // gives ptxas freedom to overlap late LDSMs with early MMAs.
        uint32_t a[2][4][4], b[2][2][4];
#pragma unroll
        for (int kk = 0; kk < 2; kk++) {
            const uint32_t ko = (uint32_t)(kk * 32);
#pragma unroll
            for (int mi = 0; mi < 4; mi++)
                ldsm4(a[kk][mi], smemBase + bb + aoff[mi] + ko);
#pragma unroll
            for (int np = 0; np < 2; np++)
                ldsm4(b[kk][np], smemBase + bb + boff[np] + ko);
        }
#pragma unroll
        for (int kk = 0; kk < 2; kk++)
#pragma unroll
            for (int mi = 0; mi < 4; mi++)
#pragma unroll
                for (int nj = 0; nj < 4; nj++) {
                    const int np = nj >> 1, hb = (nj & 1) << 1;
                    mma16(c[mi][nj], a[kk][mi], b[kk][np][hb], b[kk][np][hb + 1]);
                }
    }
}

// QKV fused projection GEMM: grid (8, 64, 3)
__global__ __launch_bounds__(256, 1)
void gemm_qkv(const __half* __restrict__ A, const __half* __restrict__ W,
              const float* __restrict__ bq, const float* __restrict__ bv,
              __half* __restrict__ Q, __half* __restrict__ K, __half* __restrict__ Vt)
{
    extern __shared__ char smc[];
    const uint32_t smemBase = (uint32_t)__cvta_generic_to_shared(smc);

    const int tid  = threadIdx.x;
    const int warp = tid >> 5;
    const int lane = tid & 31;
    const int z    = blockIdx.z;
    const int rowBase = blockIdx.y * 128;
    const int colBase = blockIdx.x * 128;

    uint32_t aoff[4], boff[2];
    frag_offsets(warp, lane, aoff, boff);

    float c[4][4][4];
#pragma unroll
    for (int mi = 0; mi < 4; mi++)
#pragma unroll
        for (int nj = 0; nj < 4; nj++)
#pragma unroll
            for (int r = 0; r < 4; r++) c[mi][nj][r] = 0.f;

    gemm_core(A, W + (size_t)z * EE * EE, c, smemBase, tid, rowBase, colBase, aoff, boff);

    const float* bias = (z == 0) ? bq : (z == 2) ? bv : nullptr;
    const int nW = (warp & 3) * 32;
    const int mW = (warp >> 2) * 64;

    if (z != 2) {
        __half* Cp = (z == 0) ? Q : K;
#pragma unroll
        for (int nj = 0; nj < 4; nj++) {
            const int col = colBase + nW + nj * 8 + (lane & 3) * 2;
            const float b0 = bias ? bias[col]     : 0.f;
            const float b1 = bias ? bias[col + 1] : 0.f;
#pragma unroll
            for (int mi = 0; mi < 4; mi++) {
                const int row = rowBase + mW + mi * 16 + (lane >> 2);
                *(__half2*)&Cp[(size_t)row * EE + col] =
                    __floats2half2_rn(c[mi][nj][0] + b0, c[mi][nj][1] + b1);
                *(__half2*)&Cp[(size_t)(row + 8) * EE + col] =
                    __floats2half2_rn(c[mi][nj][2] + b0, c[mi][nj][3] + b1);
            }
        }
    } else {
        // V: transpose through smem, then coalesced stores to Vt[col][token]
        __syncthreads();                 // pipeline smem dead now
        __half* st = (__half*)smc;       // [128 cols][136]
#pragma unroll
        for (int nj = 0; nj < 4; nj++) {
            const int cl = nW + nj * 8 + (lane & 3) * 2;
            const float b0 = bias[colBase + cl];
            const float b1 = bias[colBase + cl + 1];
#pragma unroll
            for (int mi = 0; mi < 4; mi++) {
                const int rl = mW + mi * 16 + (lane >> 2);
                st[cl * 136 + rl]           = __float2half_rn(c[mi][nj][0] + b0);
                st[(cl + 1) * 136 + rl]     = __float2half_rn(c[mi][nj][1] + b1);
                st[cl * 136 + rl + 8]       = __float2half_rn(c[mi][nj][2] + b0);
                st[(cl + 1) * 136 + rl + 8] = __float2half_rn(c[mi][nj][3] + b1);
            }
        }
        __syncthreads();
        const int col = tid >> 1;
        const int ro  = (tid & 1) * 64;
        const __half* src = &st[col * 136 + ro];
        __half* dst = &Vt[(size_t)(colBase + col) * TT + rowBase + ro];
#pragma unroll
        for (int p = 0; p < 8; p++)
            *(uint4*)(dst + 8 * p) = *(const uint4*)(src + 8 * p);
    }
}

// Output projection GEMM: C float + bias
__global__ __launch_bounds__(256, 1)
void gemm_out(const __half* __restrict__ A, const __half* __restrict__ B,
              const float* __restrict__ bias, float* __restrict__ C)
{
    extern __shared__ char smc[];
    const uint32_t smemBase = (uint32_t)__cvta_generic_to_shared(smc);

    const int tid  = threadIdx.x;
    const int warp = tid >> 5;
    const int lane = tid & 31;
    const int rowBase = blockIdx.y * 128;
    const int colBase = blockIdx.x * 128;

    uint32_t aoff[4], boff[2];
    frag_offsets(warp, lane, aoff, boff);

    float c[4][4][4];
#pragma unroll
    for (int mi = 0; mi < 4; mi++)
#pragma unroll
        for (int nj = 0; nj < 4; nj++)
#pragma unroll
            for (int r = 0; r < 4; r++) c[mi][nj][r] = 0.f;

    gemm_core(A, B, c, smemBase, tid, rowBase, colBase, aoff, boff);

    const int nW = (warp & 3) * 32;
    const int mW = (warp >> 2) * 64;
#pragma unroll
    for (int nj = 0; nj < 4; nj++) {
        const int col = colBase + nW + nj * 8 + (lane & 3) * 2;
        const float b0 = bias[col], b1 = bias[col + 1];
#pragma unroll
        for (int mi = 0; mi < 4; mi++) {
            const int row = rowBase + mW + mi * 16 + (lane >> 2);
            *(float2*)&C[(size_t)row * EE + col] =
                make_float2(c[mi][nj][0] + b0, c[mi][nj][1] + b1);
            *(float2*)&C[(size_t)(row + 8) * EE + col] =
                make_float2(c[mi][nj][2] + b0, c[mi][nj][3] + b1);
        }
    }
}

// ---------------------------------------------------------------------------
// FP16 tensor-core flash attention (unchanged from round 9).
// ---------------------------------------------------------------------------
#define AS      72
#define QBYTES  (128 * AS * 2)
#define KVBYTES (64 * AS * 2)
#define KOFFB(b) (QBYTES + (b) * 2 * KVBYTES)
#define VOFFB(b) (KOFFB(b) + KVBYTES)
#define SOFFB   (QBYTES + 4 * KVBYTES)

__global__ __launch_bounds__(256, 2)
void attn_h(const float* __restrict__ mask)
{
    extern __shared__ char smc[];
    __half* Qs = (__half*)smc;
    __half* Ss = (__half*)(smc + SOFFB);
    const uint32_t smemBase = (uint32_t)__cvta_generic_to_shared(smc);

    const int seg = blockIdx.z;
    const int h   = blockIdx.y;
    const int q0  = blockIdx.x * 128;
    const int tid = threadIdx.x;
    const int warp = tid >> 5;
    const int lane = tid & 31;
    const int r0 = lane >> 2;
    const int cb = (lane & 3) * 2;

    for (int i = tid; i < 128 * 8; i += 256) {
        const int r = i >> 3, c8 = (i & 7) * 8;
        *(uint4*)&Qs[r * AS + c8] =
            *(const uint4*)&g_qh[(size_t)(seg * LL + q0 + r) * EE + h * DD + c8];
    }

    const uint32_t qoff = smemBase + (uint32_t)(((warp * 16 + (lane & 15)) * AS
                                                 + ((lane >> 4) << 3)) << 1);
    const uint32_t poff = qoff + (uint32_t)SOFFB;
    uint32_t kvoff[4];
#pragma unroll
    for (int np = 0; np < 4; np++)
        kvoff[np] = (uint32_t)(((np * 16 + (lane & 7) + ((lane >> 4) << 3)) * AS
                                + (((lane >> 3) & 1) << 3)) << 1);

    const int ch0 = tid * 2;
    const __half* kbase = &g_kh[(size_t)(seg * LL) * EE + h * DD];
    const __half* vbase = &g_vth[(size_t)(h * DD) * TT + seg * LL];

    float o[8][4];
#pragma unroll
    for (int nj = 0; nj < 8; nj++)
#pragma unroll
        for (int r = 0; r < 4; r++) o[nj][r] = 0.f;
    float mrow[2] = {-INFINITY, -INFINITY};
    float lrow[2] = {0.f, 0.f};

    {
#pragma unroll
        for (int u = 0; u < 2; u++) {
            const int ch = ch0 + u;
            const int r = ch >> 3, c8 = (ch & 7) * 8;
            cp_async16(smemBase + KOFFB(0) + (uint32_t)((r * AS + c8) << 1),
                       kbase + (size_t)r * EE + c8);
            cp_async16(smemBase + VOFFB(0) + (uint32_t)((r * AS + c8) << 1),
                       vbase + (size_t)r * TT + c8);
        }
        cp_commit();
    }

    for (int kt = 0; kt < 16; kt++) {
        const int k0 = kt * 64;
        cp_wait<0>();
        __syncthreads();

        if (kt + 1 < 16) {
            const int kn = (kt + 1) * 64;
            const uint32_t kb = smemBase + KOFFB((kt + 1) & 1);
            const uint32_t vb = smemBase + VOFFB((kt + 1) & 1);
#pragma unroll
            for (int u = 0; u < 2; u++) {
                const int ch = ch0 + u;
                const int r = ch >> 3, c8 = (ch & 7) * 8;
                cp_async16(kb + (uint32_t)((r * AS + c8) << 1),
                           kbase + (size_t)(kn + r) * EE + c8);
                cp_async16(vb + (uint32_t)((r * AS + c8) << 1),
                           vbase + (size_t)r * TT + kn + c8);
            }
        }
        cp_commit();

        const uint32_t kbuf = smemBase + KOFFB(kt & 1);
        const uint32_t vbuf = smemBase + VOFFB(kt & 1);

        float s[8][4];
#pragma unroll
        for (int nj = 0; nj < 8; nj++)
#pragma unroll
            for (int r = 0; r < 4; r++) s[nj][r] = 0.f;

#pragma unroll
        for (int kd = 0; kd < 4; kd++) {
            const uint32_t ko = (uint32_t)(kd * 32);
            uint32_t a[4], b[4][4];
            ldsm4(a, qoff + ko);
#pragma unroll
            for (int np = 0; np < 4; np++) ldsm4(b[np], kbuf + kvoff[np] + ko);
#pragma unroll
            for (int nj = 0; nj < 8; nj++) {
                const int np = nj >> 1, hb = (nj & 1) << 1;
                mma16(s[nj], a, b[np][hb], b[np][hb + 1]);
            }
        }

        {
            const size_t mbase = (size_t)(seg * LL + q0 + warp * 16 + r0) * TT
                               + (size_t)(seg * LL + k0) + cb;
#pragma unroll
            for (int nj = 0; nj < 8; nj++) {
                float2 m0 = *(const float2*)&mask[mbase + nj * 8];
                float2 m1 = *(const float2*)&mask[mbase + nj * 8 + (size_t)8 * TT];
                s[nj][0] = s[nj][0] * 0.125f + m0.x;
                s[nj][1] = s[nj][1] * 0.125f + m0.y;
                s[nj][2] = s[nj][2] * 0.125f + m1.x;
                s[nj][3] = s[nj][3] * 0.125f + m1.y;
            }
        }

        float mx0 = s[0][0], mx1 = s[0][2];
#pragma unroll
        for (int nj = 0; nj < 8; nj++) {
            mx0 = fmaxf(mx0, fmaxf(s[nj][0], s[nj][1]));
            mx1 = fmaxf(mx1, fmaxf(s[nj][2], s[nj][3]));
        }
        mx0 = fmaxf(mx0, __shfl_xor_sync(0xffffffffu, mx0, 1));
        mx0 = fmaxf(mx0, __shfl_xor_sync(0xffffffffu, mx0, 2));
        mx1 = fmaxf(mx1, __shfl_xor_sync(0xffffffffu, mx1, 1));
        mx1 = fmaxf(mx1, __shfl_xor_sync(0xffffffffu, mx1, 2));

        const float mn0 = fmaxf(mrow[0], mx0);
        const float mn1 = fmaxf(mrow[1], mx1);
        const float al0 = __expf(mrow[0] - mn0);
        const float al1 = __expf(mrow[1] - mn1);
        mrow[0] = mn0; mrow[1] = mn1;

        float sum0 = 0.f, sum1 = 0.f;
#pragma unroll
        for (int nj = 0; nj < 8; nj++) {
            s[nj][0] = __expf(s[nj][0] - mn0); sum0 += s[nj][0];
            s[nj][1] = __expf(s[nj][1] - mn0); sum0 += s[nj][1];
            s[nj][2] = __expf(s[nj][2] - mn1); sum1 += s[nj][2];
            s[nj][3] = __expf(s[nj][3] - mn1); sum1 += s[nj][3];
        }
        sum0 += __shfl_xor_sync(0xffffffffu, sum0, 1);
        sum0 += __shfl_xor_sync(0xffffffffu, sum0, 2);
        sum1 += __shfl_xor_sync(0xffffffffu, sum1, 1);
        sum1 += __shfl_xor_sync(0xffffffffu, sum1, 2);
        lrow[0] = lrow[0] * al0 + sum0;
        lrow[1] = lrow[1] * al1 + sum1;

#pragma unroll
        for (int nj = 0; nj < 8; nj++) {
            o[nj][0] *= al0; o[nj][1] *= al0;
            o[nj][2] *= al1; o[nj][3] *= al1;
        }

        {
            __half* p0 = &Ss[(warp * 16 + r0) * AS + cb];
            __half* p1 = &Ss[(warp * 16 + r0 + 8) * AS + cb];
#pragma unroll
            for (int nj = 0; nj < 8; nj++) {
                *(__half2*)(p0 + nj * 8) = __floats2half2_rn(s[nj][0], s[nj][1]);
                *(__half2*)(p1 + nj * 8) = __floats2half2_rn(s[nj][2], s[nj][3]);
            }
        }
        __syncwarp();

#pragma unroll
        for (int kc = 0; kc < 4; kc++) {
            const uint32_t ko = (uint32_t)(kc * 32);
            uint32_t a[4], b[4][4];
            ldsm4(a, poff + ko);
#pragma unroll
            for (int np = 0; np < 4; np++) ldsm4(b[np], vbuf + kvoff[np] + ko);
#pragma unroll
            for (int nj = 0; nj < 8; nj++) {
                const int np = nj >> 1, hb = (nj & 1) << 1;
                mma16(o[nj], a, b[np][hb], b[np][hb + 1]);
            }
        }
    }

    {
        const float inv0 = 1.f / lrow[0];
        const float inv1 = 1.f / lrow[1];
        const size_t row0 = (size_t)(seg * LL + q0 + warp * 16 + r0);
#pragma unroll
        for (int nj = 0; nj < 8; nj++) {
            const int col = h * DD + nj * 8 + cb;
            *(__half2*)&g_oh[row0 * EE + col] =
                __floats2half2_rn(o[nj][0] * inv0, o[nj][1] * inv0);
            *(__half2*)&g_oh[(row0 + 8) * EE + col] =
                __floats2half2_rn(o[nj][2] * inv1, o[nj][3] * inv1);
        }
    }
}

// ---------------------------------------------------------------------------

extern "C" void kernel_launch(void* const* d_in, const int* in_sizes, int n_in,
                              void* d_out, int out_size)
{
    const float* hs   = (const float*)d_in[0];
    const float* mask = (const float*)d_in[2];
    const float* wq   = (const float*)d_in[3];
    const float* bq   = (const float*)d_in[4];
    const float* wk   = (const float*)d_in[5];
    const float* wv   = (const float*)d_in[6];
    const float* bv   = (const float*)d_in[7];
    const float* wo   = (const float*)d_in[8];
    const float* bo   = (const float*)d_in[9];
    float* out = (float*)d_out;

    __half *hh, *wh, *qh, *kh, *vth, *oh;
    cudaGetSymbolAddress((void**)&hh,  g_hh);
    cudaGetSymbolAddress((void**)&wh,  g_wh);
    cudaGetSymbolAddress((void**)&qh,  g_qh);
    cudaGetSymbolAddress((void**)&kh,  g_kh);
    cudaGetSymbolAddress((void**)&vth, g_vth);
    cudaGetSymbolAddress((void**)&oh,  g_oh);

    const int gsmem = NSTAGE * STGB;              // 122880
    cudaFuncSetAttribute(gemm_qkv, cudaFuncAttributeMaxDynamicSharedMemorySize, gsmem);
    cudaFuncSetAttribute(gemm_out, cudaFuncAttributeMaxDynamicSharedMemorySize, gsmem);
    const int asmem = SOFFB + QBYTES;
    cudaFuncSetAttribute(attn_h, cudaFuncAttributeMaxDynamicSharedMemorySize, asmem);

    const int nConv = (TT * EE + 4 * EE * EE) / 4;
    f2h_all<<<nConv / 256, 256>>>(hs, wq, wk, wv, wo, hh, wh);

    gemm_qkv<<<dim3(EE / 128, TT / 128, 3), 256, gsmem>>>(hh, wh, bq, bv, qh, kh, vth);

    attn_h<<<dim3(LL / 128, HH, NSEG), 256, asmem>>>(mask);

    gemm_out<<<dim3(EE / 128, TT / 128), 256, gsmem>>>(oh, wh + 3 * (size_t)EE * EE, bo, out);
}

// round 11
// speedup vs baseline: 1.0956x; 1.0956x over previous
#include <cuda_runtime.h>
#include <cuda_fp16.h>
#include <math.h>
#include <stdint.h>

#define TT   8192
#define EE   1024
#define HH   16
#define DD   64
#define NSEG 8
#define LL   1024

// Scratch (device globals — no allocation allowed in kernel_launch)
__device__ __half g_hh [TT * EE];       // hs in half
__device__ __half g_wh [4 * EE * EE];   // 4 weights in half
__device__ __half g_qh [TT * EE];       // Q projection (half)
__device__ __half g_kh [TT * EE];       // K projection (half)
__device__ __half g_vth[EE * TT];       // V projection, transposed [e][token]
__device__ __half g_oh [TT * EE];       // attention output (half)

// ---------------------------------------------------------------------------
// helpers
// ---------------------------------------------------------------------------
__device__ __forceinline__ void ldsm4(uint32_t* r, uint32_t addr) {
    asm volatile("ldmatrix.sync.aligned.m8n8.x4.shared.b16 {%0,%1,%2,%3}, [%4];"
                 : "=r"(r[0]), "=r"(r[1]), "=r"(r[2]), "=r"(r[3]) : "r"(addr));
}
__device__ __forceinline__ void mma16(float* c, const uint32_t* a, uint32_t b0, uint32_t b1) {
    asm volatile("mma.sync.aligned.m16n8k16.row.col.f32.f16.f16.f32 "
                 "{%0,%1,%2,%3}, {%4,%5,%6,%7}, {%8,%9}, {%0,%1,%2,%3};"
                 : "+f"(c[0]), "+f"(c[1]), "+f"(c[2]), "+f"(c[3])
                 : "r"(a[0]), "r"(a[1]), "r"(a[2]), "r"(a[3]), "r"(b0), "r"(b1));
}
__device__ __forceinline__ void cp_async16(uint32_t dst, const void* src) {
    asm volatile("cp.async.cg.shared.global [%0], [%1], 16;\n" :: "r"(dst), "l"(src));
}
__device__ __forceinline__ void cp_commit() { asm volatile("cp.async.commit_group;\n"); }
template <int N> __device__ __forceinline__ void cp_wait() {
    asm volatile("cp.async.wait_group %0;\n" :: "n"(N));
}

// ---------------------------------------------------------------------------
// fused float -> half conversion
// ---------------------------------------------------------------------------
__global__ void f2h_all(const float* __restrict__ hs,
                        const float* __restrict__ w0, const float* __restrict__ w1,
                        const float* __restrict__ w2, const float* __restrict__ w3,
                        __half* __restrict__ hh, __half* __restrict__ wh)
{
    const int nAct4 = TT * EE / 4;
    const int nW4   = EE * EE / 4;
    int i = blockIdx.x * blockDim.x + threadIdx.x;

    const float* src; __half* dst; int j;
    if (i < nAct4) { src = hs; dst = hh; j = i; }
    else {
        int t = i - nAct4;
        int w = t / nW4;
        j = t - w * nW4;
        src = (w == 0) ? w0 : (w == 1) ? w1 : (w == 2) ? w2 : w3;
        dst = wh + (size_t)w * EE * EE;
    }
    float4 v = ((const float4*)src)[j];
    __half2* o = (__half2*)dst;
    o[2 * j]     = __floats2half2_rn(v.x, v.y);
    o[2 * j + 1] = __floats2half2_rn(v.z, v.w);
}

// ---------------------------------------------------------------------------
// FP16 mma.sync GEMM core (round-9 config): 128x128 tile, BK=32,
// 5-stage cp.async, ONE barrier per slab. 8 warps (2x4), warp 64x32, 2 CTA/SM.
// ---------------------------------------------------------------------------
#define GH      40
#define ABY     (128 * GH * 2)            // 10240
#define STGB    (2 * ABY)                 // 20480
#define NSTAGE  5
#define NSLAB   (EE / 32)                 // 32

__device__ __forceinline__ void frag_offsets(int warp, int lane, uint32_t* aoff, uint32_t* boff)
{
    const int mW = (warp >> 2) * 64;
    const int nW = (warp & 3) * 32;
#pragma unroll
    for (int mi = 0; mi < 4; mi++)
        aoff[mi] = (uint32_t)(((mW + mi * 16 + (lane & 15)) * GH + ((lane >> 4) << 3)) << 1);
#pragma unroll
    for (int np = 0; np < 2; np++)
        boff[np] = (uint32_t)(((nW + np * 16 + (lane & 7) + ((lane >> 4) << 3)) * GH
                               + (((lane >> 3) & 1) << 3)) << 1) + ABY;
}

__device__ __forceinline__ void gemm_core(
    const __half* __restrict__ A, const __half* __restrict__ B, float c[4][4][4],
    uint32_t smemBase, int tid, int rowBase, int colBase,
    const uint32_t* aoff, const uint32_t* boff)
{
    const int lr = tid >> 1;
    const int lc = (tid & 1) * 8;
    const __half* Aptr = A + (size_t)(rowBase + lr) * EE + lc;
    const __half* Bptr = B + (size_t)(colBase + lr) * EE + lc;
    const uint32_t sA = smemBase + (uint32_t)((lr * GH + lc) * 2);
    const uint32_t sB = sA + ABY;

#pragma unroll
    for (int st = 0; st < NSTAGE - 1; st++) {
        const uint32_t bb = st * STGB;
        const int k0 = st * 32;
        cp_async16(sA + bb,      Aptr + k0);
        cp_async16(sA + bb + 32, Aptr + k0 + 16);
        cp_async16(sB + bb,      Bptr + k0);
        cp_async16(sB + bb + 32, Bptr + k0 + 16);
        cp_commit();
    }

    for (int s = 0; s < NSLAB; s++) {
        cp_wait<NSTAGE - 2>();     // slab s resident
        __syncthreads();           // all warps done reading buffer being refilled

        const int sn = s + NSTAGE - 1;
        if (sn < NSLAB) {
            const uint32_t nb = (uint32_t)(sn % NSTAGE) * STGB;
            const int k0 = sn * 32;
            cp_async16(sA + nb,      Aptr + k0);
            cp_async16(sA + nb + 32, Aptr + k0 + 16);
            cp_async16(sB + nb,      Bptr + k0);
            cp_async16(sB + nb + 32, Bptr + k0 + 16);
        }
        cp_commit();

        const uint32_t bb = (uint32_t)(s % NSTAGE) * STGB;
#pragma unroll
        for (int kk = 0; kk < 2; kk++) {
            const uint32_t ko = (uint32_t)(kk * 32);
            uint32_t a[4][4], b[2][4];
#pragma unroll
            for (int mi = 0; mi < 4; mi++)
                ldsm4(a[mi], smemBase + bb + aoff[mi] + ko);
#pragma unroll
            for (int np = 0; np < 2; np++)
                ldsm4(b[np], smemBase + bb + boff[np] + ko);
#pragma unroll
            for (int mi = 0; mi < 4; mi++)
#pragma unroll
                for (int nj = 0; nj < 4; nj++) {
                    const int np = nj >> 1, hb = (nj & 1) << 1;
                    mma16(c[mi][nj], a[mi], b[np][hb], b[np][hb + 1]);
                }
        }
    }
}

// QKV fused projection GEMM: grid (8, 64, 3)
__global__ __launch_bounds__(256, 2)
void gemm_qkv(const __half* __restrict__ A, const __half* __restrict__ W,
              const float* __restrict__ bq, const float* __restrict__ bv,
              __half* __restrict__ Q, __half* __restrict__ K, __half* __restrict__ Vt)
{
    extern __shared__ char smc[];
    const uint32_t smemBase = (uint32_t)__cvta_generic_to_shared(smc);

    const int tid  = threadIdx.x;
    const int warp = tid >> 5;
    const int lane = tid & 31;
    const int z    = blockIdx.z;
    const int rowBase = blockIdx.y * 128;
    const int colBase = blockIdx.x * 128;

    uint32_t aoff[4], boff[2];
    frag_offsets(warp, lane, aoff, boff);

    float c[4][4][4];
#pragma unroll
    for (int mi = 0; mi < 4; mi++)
#pragma unroll
        for (int nj = 0; nj < 4; nj++)
#pragma unroll
            for (int r = 0; r < 4; r++) c[mi][nj][r] = 0.f;

    gemm_core(A, W + (size_t)z * EE * EE, c, smemBase, tid, rowBase, colBase, aoff, boff);

    const float* bias = (z == 0) ? bq : (z == 2) ? bv : nullptr;
    const int nW = (warp & 3) * 32;
    const int mW = (warp >> 2) * 64;

    if (z != 2) {
        __half* Cp = (z == 0) ? Q : K;
#pragma unroll
        for (int nj = 0; nj < 4; nj++) {
            const int col = colBase + nW + nj * 8 + (lane & 3) * 2;
            const float b0 = bias ? bias[col]     : 0.f;
            const float b1 = bias ? bias[col + 1] : 0.f;
#pragma unroll
            for (int mi = 0; mi < 4; mi++) {
                const int row = rowBase + mW + mi * 16 + (lane >> 2);
                *(__half2*)&Cp[(size_t)row * EE + col] =
                    __floats2half2_rn(c[mi][nj][0] + b0, c[mi][nj][1] + b1);
                *(__half2*)&Cp[(size_t)(row + 8) * EE + col] =
                    __floats2half2_rn(c[mi][nj][2] + b0, c[mi][nj][3] + b1);
            }
        }
    } else {
        // V: transpose through smem, then coalesced stores to Vt[col][token]
        __syncthreads();                 // pipeline smem dead now
        __half* st = (__half*)smc;       // [128 cols][136]
#pragma unroll
        for (int nj = 0; nj < 4; nj++) {
            const int cl = nW + nj * 8 + (lane & 3) * 2;
            const float b0 = bias[colBase + cl];
            const float b1 = bias[colBase + cl + 1];
#pragma unroll
            for (int mi = 0; mi < 4; mi++) {
                const int rl = mW + mi * 16 + (lane >> 2);
                st[cl * 136 + rl]           = __float2half_rn(c[mi][nj][0] + b0);
                st[(cl + 1) * 136 + rl]     = __float2half_rn(c[mi][nj][1] + b1);
                st[cl * 136 + rl + 8]       = __float2half_rn(c[mi][nj][2] + b0);
                st[(cl + 1) * 136 + rl + 8] = __float2half_rn(c[mi][nj][3] + b1);
            }
        }
        __syncthreads();
        const int col = tid >> 1;
        const int ro  = (tid & 1) * 64;
        const __half* src = &st[col * 136 + ro];
        __half* dst = &Vt[(size_t)(colBase + col) * TT + rowBase + ro];
#pragma unroll
        for (int p = 0; p < 8; p++)
            *(uint4*)(dst + 8 * p) = *(const uint4*)(src + 8 * p);
    }
}

// Output projection GEMM: C float + bias
__global__ __launch_bounds__(256, 2)
void gemm_out(const __half* __restrict__ A, const __half* __restrict__ B,
              const float* __restrict__ bias, float* __restrict__ C)
{
    extern __shared__ char smc[];
    const uint32_t smemBase = (uint32_t)__cvta_generic_to_shared(smc);

    const int tid  = threadIdx.x;
    const int warp = tid >> 5;
    const int lane = tid & 31;
    const int rowBase = blockIdx.y * 128;
    const int colBase = blockIdx.x * 128;

    uint32_t aoff[4], boff[2];
    frag_offsets(warp, lane, aoff, boff);

    float c[4][4][4];
#pragma unroll
    for (int mi = 0; mi < 4; mi++)
#pragma unroll
        for (int nj = 0; nj < 4; nj++)
#pragma unroll
            for (int r = 0; r < 4; r++) c[mi][nj][r] = 0.f;

    gemm_core(A, B, c, smemBase, tid, rowBase, colBase, aoff, boff);

    const int nW = (warp & 3) * 32;
    const int mW = (warp >> 2) * 64;
#pragma unroll
    for (int nj = 0; nj < 4; nj++) {
        const int col = colBase + nW + nj * 8 + (lane & 3) * 2;
        const float b0 = bias[col], b1 = bias[col + 1];
#pragma unroll
        for (int mi = 0; mi < 4; mi++) {
            const int row = rowBase + mW + mi * 16 + (lane >> 2);
            *(float2*)&C[(size_t)row * EE + col] =
                make_float2(c[mi][nj][0] + b0, c[mi][nj][1] + b1);
            *(float2*)&C[(size_t)(row + 8) * EE + col] =
                make_float2(c[mi][nj][2] + b0, c[mi][nj][3] + b1);
        }
    }
}

// ---------------------------------------------------------------------------
// FP16 tensor-core flash attention, 128 q-rows/CTA, 8 warps,
// double-buffered cp.async K/V, ONE barrier per ktile.
// grid (HH, LL/128, NSEG) — head fastest, so the ~296 concurrently-resident
// CTAs cover all 16 heads of the same (seg, q-block) and share mask tiles in L2.
// ---------------------------------------------------------------------------
#define AS      72
#define QBYTES  (128 * AS * 2)
#define KVBYTES (64 * AS * 2)
#define KOFFB(b) (QBYTES + (b) * 2 * KVBYTES)
#define VOFFB(b) (KOFFB(b) + KVBYTES)
#define SOFFB   (QBYTES + 4 * KVBYTES)

__global__ __launch_bounds__(256, 2)
void attn_h(const float* __restrict__ mask)
{
    extern __shared__ char smc[];
    __half* Qs = (__half*)smc;
    __half* Ss = (__half*)(smc + SOFFB);
    const uint32_t smemBase = (uint32_t)__cvta_generic_to_shared(smc);

    const int h   = blockIdx.x;          // head fastest -> mask L2 sharing
    const int q0  = blockIdx.y * 128;
    const int seg = blockIdx.z;
    const int tid = threadIdx.x;
    const int warp = tid >> 5;
    const int lane = tid & 31;
    const int r0 = lane >> 2;
    const int cb = (lane & 3) * 2;

    for (int i = tid; i < 128 * 8; i += 256) {
        const int r = i >> 3, c8 = (i & 7) * 8;
        *(uint4*)&Qs[r * AS + c8] =
            *(const uint4*)&g_qh[(size_t)(seg * LL + q0 + r) * EE + h * DD + c8];
    }

    const uint32_t qoff = smemBase + (uint32_t)(((warp * 16 + (lane & 15)) * AS
                                                 + ((lane >> 4) << 3)) << 1);
    const uint32_t poff = qoff + (uint32_t)SOFFB;
    uint32_t kvoff[4];
#pragma unroll
    for (int np = 0; np < 4; np++)
        kvoff[np] = (uint32_t)(((np * 16 + (lane & 7) + ((lane >> 4) << 3)) * AS
                                + (((lane >> 3) & 1) << 3)) << 1);

    const int ch0 = tid * 2;
    const __half* kbase = &g_kh[(size_t)(seg * LL) * EE + h * DD];
    const __half* vbase = &g_vth[(size_t)(h * DD) * TT + seg * LL];

    float o[8][4];
#pragma unroll
    for (int nj = 0; nj < 8; nj++)
#pragma unroll
        for (int r = 0; r < 4; r++) o[nj][r] = 0.f;
    float mrow[2] = {-INFINITY, -INFINITY};
    float lrow[2] = {0.f, 0.f};

    {
#pragma unroll
        for (int u = 0; u < 2; u++) {
            const int ch = ch0 + u;
            const int r = ch >> 3, c8 = (ch & 7) * 8;
            cp_async16(smemBase + KOFFB(0) + (uint32_t)((r * AS + c8) << 1),
                       kbase + (size_t)r * EE + c8);
            cp_async16(smemBase + VOFFB(0) + (uint32_t)((r * AS + c8) << 1),
                       vbase + (size_t)r * TT + c8);
        }
        cp_commit();
    }

    for (int kt = 0; kt < 16; kt++) {
        const int k0 = kt * 64;
        cp_wait<0>();
        __syncthreads();

        if (kt + 1 < 16) {
            const int kn = (kt + 1) * 64;
            const uint32_t kb = smemBase + KOFFB((kt + 1) & 1);
            const uint32_t vb = smemBase + VOFFB((kt + 1) & 1);
#pragma unroll
            for (int u = 0; u < 2; u++) {
                const int ch = ch0 + u;
                const int r = ch >> 3, c8 = (ch & 7) * 8;
                cp_async16(kb + (uint32_t)((r * AS + c8) << 1),
                           kbase + (size_t)(kn + r) * EE + c8);
                cp_async16(vb + (uint32_t)((r * AS + c8) << 1),
                           vbase + (size_t)r * TT + kn + c8);
            }
        }
        cp_commit();

        const uint32_t kbuf = smemBase + KOFFB(kt & 1);
        const uint32_t vbuf = smemBase + VOFFB(kt & 1);

        float s[8][4];
#pragma unroll
        for (int nj = 0; nj < 8; nj++)
#pragma unroll
            for (int r = 0; r < 4; r++) s[nj][r] = 0.f;

#pragma unroll
        for (int kd = 0; kd < 4; kd++) {
            const uint32_t ko = (uint32_t)(kd * 32);
            uint32_t a[4], b[4][4];
            ldsm4(a, qoff + ko);
#pragma unroll
            for (int np = 0; np < 4; np++) ldsm4(b[np], kbuf + kvoff[np] + ko);
#pragma unroll
            for (int nj = 0; nj < 8; nj++) {
                const int np = nj >> 1, hb = (nj & 1) << 1;
                mma16(s[nj], a, b[np][hb], b[np][hb + 1]);
            }
        }

        {
            const size_t mbase = (size_t)(seg * LL + q0 + warp * 16 + r0) * TT
                               + (size_t)(seg * LL + k0) + cb;
#pragma unroll
            for (int nj = 0; nj < 8; nj++) {
                float2 m0 = *(const float2*)&mask[mbase + nj * 8];
                float2 m1 = *(const float2*)&mask[mbase + nj * 8 + (size_t)8 * TT];
                s[nj][0] = s[nj][0] * 0.125f + m0.x;
                s[nj][1] = s[nj][1] * 0.125f + m0.y;
                s[nj][2] = s[nj][2] * 0.125f + m1.x;
                s[nj][3] = s[nj][3] * 0.125f + m1.y;
            }
        }

        float mx0 = s[0][0], mx1 = s[0][2];
#pragma unroll
        for (int nj = 0; nj < 8; nj++) {
            mx0 = fmaxf(mx0, fmaxf(s[nj][0], s[nj][1]));
            mx1 = fmaxf(mx1, fmaxf(s[nj][2], s[nj][3]));
        }
        mx0 = fmaxf(mx0, __shfl_xor_sync(0xffffffffu, mx0, 1));
        mx0 = fmaxf(mx0, __shfl_xor_sync(0xffffffffu, mx0, 2));
        mx1 = fmaxf(mx1, __shfl_xor_sync(0xffffffffu, mx1, 1));
        mx1 = fmaxf(mx1, __shfl_xor_sync(0xffffffffu, mx1, 2));

        const float mn0 = fmaxf(mrow[0], mx0);
        const float mn1 = fmaxf(mrow[1], mx1);
        const float al0 = __expf(mrow[0] - mn0);
        const float al1 = __expf(mrow[1] - mn1);
        mrow[0] = mn0; mrow[1] = mn1;

        float sum0 = 0.f, sum1 = 0.f;
#pragma unroll
        for (int nj = 0; nj < 8; nj++) {
            s[nj][0] = __expf(s[nj][0] - mn0); sum0 += s[nj][0];
            s[nj][1] = __expf(s[nj][1] - mn0); sum0 += s[nj][1];
            s[nj][2] = __expf(s[nj][2] - mn1); sum1 += s[nj][2];
            s[nj][3] = __expf(s[nj][3] - mn1); sum1 += s[nj][3];
        }
        sum0 += __shfl_xor_sync(0xffffffffu, sum0, 1);
        sum0 += __shfl_xor_sync(0xffffffffu, sum0, 2);
        sum1 += __shfl_xor_sync(0xffffffffu, sum1, 1);
        sum1 += __shfl_xor_sync(0xffffffffu, sum1, 2);
        lrow[0] = lrow[0] * al0 + sum0;
        lrow[1] = lrow[1] * al1 + sum1;

#pragma unroll
        for (int nj = 0; nj < 8; nj++) {
            o[nj][0] *= al0; o[nj][1] *= al0;
            o[nj][2] *= al1; o[nj][3] *= al1;
        }

        {
            __half* p0 = &Ss[(warp * 16 + r0) * AS + cb];
            __half* p1 = &Ss[(warp * 16 + r0 + 8) * AS + cb];
#pragma unroll
            for (int nj = 0; nj < 8; nj++) {
                *(__half2*)(p0 + nj * 8) = __floats2half2_rn(s[nj][0], s[nj][1]);
                *(__half2*)(p1 + nj * 8) = __floats2half2_rn(s[nj][2], s[nj][3]);
            }
        }
        __syncwarp();

#pragma unroll
        for (int kc = 0; kc < 4; kc++) {
            const uint32_t ko = (uint32_t)(kc * 32);
            uint32_t a[4], b[4][4];
            ldsm4(a, poff + ko);
#pragma unroll
            for (int np = 0; np < 4; np++) ldsm4(b[np], vbuf + kvoff[np] + ko);
#pragma unroll
            for (int nj = 0; nj < 8; nj++) {
                const int np = nj >> 1, hb = (nj & 1) << 1;
                mma16(o[nj], a, b[np][hb], b[np][hb + 1]);
            }
        }
    }

    {
        const float inv0 = 1.f / lrow[0];
        const float inv1 = 1.f / lrow[1];
        const size_t row0 = (size_t)(seg * LL + q0 + warp * 16 + r0);
#pragma unroll
        for (int nj = 0; nj < 8; nj++) {
            const int col = h * DD + nj * 8 + cb;
            *(__half2*)&g_oh[row0 * EE + col] =
                __floats2half2_rn(o[nj][0] * inv0, o[nj][1] * inv0);
            *(__half2*)&g_oh[(row0 + 8) * EE + col] =
                __floats2half2_rn(o[nj][2] * inv1, o[nj][3] * inv1);
        }
    }
}

// ---------------------------------------------------------------------------

extern "C" void kernel_launch(void* const* d_in, const int* in_sizes, int n_in,
                              void* d_out, int out_size)
{
    const float* hs   = (const float*)d_in[0];
    const float* mask = (const float*)d_in[2];
    const float* wq   = (const float*)d_in[3];
    const float* bq   = (const float*)d_in[4];
    const float* wk   = (const float*)d_in[5];
    const float* wv   = (const float*)d_in[6];
    const float* bv   = (const float*)d_in[7];
    const float* wo   = (const float*)d_in[8];
    const float* bo   = (const float*)d_in[9];
    float* out = (float*)d_out;

    __half *hh, *wh, *qh, *kh, *vth, *oh;
    cudaGetSymbolAddress((void**)&hh,  g_hh);
    cudaGetSymbolAddress((void**)&wh,  g_wh);
    cudaGetSymbolAddress((void**)&qh,  g_qh);
    cudaGetSymbolAddress((void**)&kh,  g_kh);
    cudaGetSymbolAddress((void**)&vth, g_vth);
    cudaGetSymbolAddress((void**)&oh,  g_oh);

    const int gsmem = NSTAGE * STGB;              // 102400
    cudaFuncSetAttribute(gemm_qkv, cudaFuncAttributeMaxDynamicSharedMemorySize, gsmem);
    cudaFuncSetAttribute(gemm_out, cudaFuncAttributeMaxDynamicSharedMemorySize, gsmem);
    const int asmem = SOFFB + QBYTES;
    cudaFuncSetAttribute(attn_h, cudaFuncAttributeMaxDynamicSharedMemorySize, asmem);

    const int nConv = (TT * EE + 4 * EE * EE) / 4;
    f2h_all<<<nConv / 256, 256>>>(hs, wq, wk, wv, wo, hh, wh);

    gemm_qkv<<<dim3(EE / 128, TT / 128, 3), 256, gsmem>>>(hh, wh, bq, bv, qh, kh, vth);

    attn_h<<<dim3(HH, LL / 128, NSEG), 256, asmem>>>(mask);

    gemm_out<<<dim3(EE / 128, TT / 128), 256, gsmem>>>(oh, wh + 3 * (size_t)EE * EE, bo, out);
}

// round 12
// speedup vs baseline: 1.2278x; 1.1207x over previous
#include <cuda_runtime.h>
#include <cuda_fp16.h>
#include <math.h>
#include <stdint.h>

#define TT   8192
#define EE   1024
#define HH   16
#define DD   64
#define NSEG 8
#define LL   1024

// Scratch (device globals — no allocation allowed in kernel_launch)
__device__ __half g_hh [TT * EE];       // hs in half
__device__ __half g_wh [4 * EE * EE];   // 4 weights in half
__device__ __half g_qh [TT * EE];       // Q projection (half)
__device__ __half g_kh [TT * EE];       // K projection (half)
__device__ __half g_vth[EE * TT];       // V projection, transposed [e][token]
__device__ __half g_oh [TT * EE];       // attention output (half)

// ---------------------------------------------------------------------------
// helpers
// ---------------------------------------------------------------------------
__device__ __forceinline__ void ldsm4(uint32_t* r, uint32_t addr) {
    asm volatile("ldmatrix.sync.aligned.m8n8.x4.shared.b16 {%0,%1,%2,%3}, [%4];"
                 : "=r"(r[0]), "=r"(r[1]), "=r"(r[2]), "=r"(r[3]) : "r"(addr));
}
__device__ __forceinline__ void mma16(float* c, const uint32_t* a, uint32_t b0, uint32_t b1) {
    asm volatile("mma.sync.aligned.m16n8k16.row.col.f32.f16.f16.f32 "
                 "{%0,%1,%2,%3}, {%4,%5,%6,%7}, {%8,%9}, {%0,%1,%2,%3};"
                 : "+f"(c[0]), "+f"(c[1]), "+f"(c[2]), "+f"(c[3])
                 : "r"(a[0]), "r"(a[1]), "r"(a[2]), "r"(a[3]), "r"(b0), "r"(b1));
}
__device__ __forceinline__ void cp_async16(uint32_t dst, const void* src) {
    asm volatile("cp.async.cg.shared.global [%0], [%1], 16;\n" :: "r"(dst), "l"(src));
}
__device__ __forceinline__ void cp_commit() { asm volatile("cp.async.commit_group;\n"); }
template <int N> __device__ __forceinline__ void cp_wait() {
    asm volatile("cp.async.wait_group %0;\n" :: "n"(N));
}

// ---------------------------------------------------------------------------
// fused float -> half conversion
// ---------------------------------------------------------------------------
__global__ void f2h_all(const float* __restrict__ hs,
                        const float* __restrict__ w0, const float* __restrict__ w1,
                        const float* __restrict__ w2, const float* __restrict__ w3,
                        __half* __restrict__ hh, __half* __restrict__ wh)
{
    const int nAct4 = TT * EE / 4;
    const int nW4   = EE * EE / 4;
    int i = blockIdx.x * blockDim.x + threadIdx.x;

    const float* src; __half* dst; int j;
    if (i < nAct4) { src = hs; dst = hh; j = i; }
    else {
        int t = i - nAct4;
        int w = t / nW4;
        j = t - w * nW4;
        src = (w == 0) ? w0 : (w == 1) ? w1 : (w == 2) ? w2 : w3;
        dst = wh + (size_t)w * EE * EE;
    }
    float4 v = ((const float4*)src)[j];
    __half2* o = (__half2*)dst;
    o[2 * j]     = __floats2half2_rn(v.x, v.y);
    o[2 * j + 1] = __floats2half2_rn(v.z, v.w);
}

// ---------------------------------------------------------------------------
// FP16 mma.sync GEMM v2: block tile 128x64, BK=32, 4-stage cp.async,
// 8 warps (4x2), warp tile 32x32, low-register (3 CTAs/SM).
// C[M,N] = A[M,K] @ B[N,K]^T (+bias). grid (N/64, M/128 [, z]).
// ---------------------------------------------------------------------------
#define GH      40
#define ABY2    (128 * GH * 2)            // 10240
#define BBY2    (64 * GH * 2)             // 5120
#define STGB2   (ABY2 + BBY2)             // 15360
#define NST2    4
#define NSLAB   (EE / 32)                 // 32

__device__ __forceinline__ void frag_offsets2(int warp, int lane, uint32_t* aoff, uint32_t* boff)
{
    const int mW = (warp >> 1) * 32;      // 4 m-groups of 32
    const int nW = (warp & 1) * 32;       // 2 n-groups of 32
#pragma unroll
    for (int mi = 0; mi < 2; mi++)
        aoff[mi] = (uint32_t)(((mW + mi * 16 + (lane & 15)) * GH + ((lane >> 4) << 3)) << 1);
#pragma unroll
    for (int np = 0; np < 2; np++)
        boff[np] = (uint32_t)(((nW + np * 16 + (lane & 7) + ((lane >> 4) << 3)) * GH
                               + (((lane >> 3) & 1) << 3)) << 1) + ABY2;
}

__device__ __forceinline__ void gemm_core2(
    const __half* __restrict__ A, const __half* __restrict__ B, float c[2][4][4],
    uint32_t smemBase, int tid, int rowBase, int colBase,
    const uint32_t* aoff, const uint32_t* boff)
{
    // loader: lr = tid>>2 (0..63), lc = (tid&3)*8 halfs (16B chunk)
    const int lr = tid >> 2;
    const int lc = (tid & 3) * 8;
    const __half* Aptr = A + (size_t)(rowBase + lr) * EE + lc;   // rows lr, lr+64
    const __half* Bptr = B + (size_t)(colBase + lr) * EE + lc;   // row lr (0..63)
    const uint32_t sA0 = smemBase + (uint32_t)((lr * GH + lc) * 2);
    const uint32_t sA1 = smemBase + (uint32_t)(((lr + 64) * GH + lc) * 2);
    const uint32_t sB0 = smemBase + ABY2 + (uint32_t)((lr * GH + lc) * 2);

#pragma unroll
    for (int st = 0; st < NST2 - 1; st++) {
        const uint32_t bb = st * STGB2;
        const int k0 = st * 32;
        cp_async16(sA0 + bb, Aptr + k0);
        cp_async16(sA1 + bb, Aptr + (size_t)64 * EE + k0);
        cp_async16(sB0 + bb, Bptr + k0);
        cp_commit();
    }

    for (int s = 0; s < NSLAB; s++) {
        cp_wait<NST2 - 2>();       // slab s resident
        __syncthreads();           // all warps done reading buffer being refilled

        const int sn = s + NST2 - 1;
        if (sn < NSLAB) {
            const uint32_t nb = (uint32_t)(sn % NST2) * STGB2;
            const int k0 = sn * 32;
            cp_async16(sA0 + nb, Aptr + k0);
            cp_async16(sA1 + nb, Aptr + (size_t)64 * EE + k0);
            cp_async16(sB0 + nb, Bptr + k0);
        }
        cp_commit();

        const uint32_t bb = (uint32_t)(s % NST2) * STGB2;
#pragma unroll
        for (int kk = 0; kk < 2; kk++) {
            const uint32_t ko = (uint32_t)(kk * 32);   // 16 halfs
            uint32_t a[2][4], b[2][4];
#pragma unroll
            for (int mi = 0; mi < 2; mi++)
                ldsm4(a[mi], smemBase + bb + aoff[mi] + ko);
#pragma unroll
            for (int np = 0; np < 2; np++)
                ldsm4(b[np], smemBase + bb + boff[np] + ko);
#pragma unroll
            for (int mi = 0; mi < 2; mi++)
#pragma unroll
                for (int nj = 0; nj < 4; nj++) {
                    const int np = nj >> 1, hb = (nj & 1) << 1;
                    mma16(c[mi][nj], a[mi], b[np][hb], b[np][hb + 1]);
                }
        }
    }
}

// QKV fused projection GEMM: grid (16, 64, 3)
__global__ __launch_bounds__(256, 3)
void gemm_qkv(const __half* __restrict__ A, const __half* __restrict__ W,
              const float* __restrict__ bq, const float* __restrict__ bv,
              __half* __restrict__ Q, __half* __restrict__ K, __half* __restrict__ Vt)
{
    extern __shared__ char smc[];
    const uint32_t smemBase = (uint32_t)__cvta_generic_to_shared(smc);

    const int tid  = threadIdx.x;
    const int warp = tid >> 5;
    const int lane = tid & 31;
    const int z    = blockIdx.z;
    const int rowBase = blockIdx.y * 128;
    const int colBase = blockIdx.x * 64;

    uint32_t aoff[2], boff[2];
    frag_offsets2(warp, lane, aoff, boff);

    float c[2][4][4];
#pragma unroll
    for (int mi = 0; mi < 2; mi++)
#pragma unroll
        for (int nj = 0; nj < 4; nj++)
#pragma unroll
            for (int r = 0; r < 4; r++) c[mi][nj][r] = 0.f;

    gemm_core2(A, W + (size_t)z * EE * EE, c, smemBase, tid, rowBase, colBase, aoff, boff);

    const float* bias = (z == 0) ? bq : (z == 2) ? bv : nullptr;
    const int mW = (warp >> 1) * 32;
    const int nW = (warp & 1) * 32;

    if (z != 2) {
        __half* Cp = (z == 0) ? Q : K;
#pragma unroll
        for (int nj = 0; nj < 4; nj++) {
            const int col = colBase + nW + nj * 8 + (lane & 3) * 2;
            const float b0 = bias ? bias[col]     : 0.f;
            const float b1 = bias ? bias[col + 1] : 0.f;
#pragma unroll
            for (int mi = 0; mi < 2; mi++) {
                const int row = rowBase + mW + mi * 16 + (lane >> 2);
                *(__half2*)&Cp[(size_t)row * EE + col] =
                    __floats2half2_rn(c[mi][nj][0] + b0, c[mi][nj][1] + b1);
                *(__half2*)&Cp[(size_t)(row + 8) * EE + col] =
                    __floats2half2_rn(c[mi][nj][2] + b0, c[mi][nj][3] + b1);
            }
        }
    } else {
        // V: transpose through smem, then coalesced stores to Vt[col][token]
        __syncthreads();                 // pipeline smem dead now
        __half* st = (__half*)smc;       // [64 cols][136]
#pragma unroll
        for (int nj = 0; nj < 4; nj++) {
            const int cl = nW + nj * 8 + (lane & 3) * 2;
            const float b0 = bias[colBase + cl];
            const float b1 = bias[colBase + cl + 1];
#pragma unroll
            for (int mi = 0; mi < 2; mi++) {
                const int rl = mW + mi * 16 + (lane >> 2);
                st[cl * 136 + rl]           = __float2half_rn(c[mi][nj][0] + b0);
                st[(cl + 1) * 136 + rl]     = __float2half_rn(c[mi][nj][1] + b1);
                st[cl * 136 + rl + 8]       = __float2half_rn(c[mi][nj][2] + b0);
                st[(cl + 1) * 136 + rl + 8] = __float2half_rn(c[mi][nj][3] + b1);
            }
        }
        __syncthreads();
        const int col = tid >> 2;              // 0..63
        const int ro  = (tid & 3) * 32;        // 4 x 32-half runs
        const __half* src = &st[col * 136 + ro];
        __half* dst = &Vt[(size_t)(colBase + col) * TT + rowBase + ro];
#pragma unroll
        for (int p = 0; p < 4; p++)
            *(uint4*)(dst + 8 * p) = *(const uint4*)(src + 8 * p);
    }
}

// Output projection GEMM: C float + bias. grid (16, 64)
__global__ __launch_bounds__(256, 3)
void gemm_out(const __half* __restrict__ A, const __half* __restrict__ B,
              const float* __restrict__ bias, float* __restrict__ C)
{
    extern __shared__ char smc[];
    const uint32_t smemBase = (uint32_t)__cvta_generic_to_shared(smc);

    const int tid  = threadIdx.x;
    const int warp = tid >> 5;
    const int lane = tid & 31;
    const int rowBase = blockIdx.y * 128;
    const int colBase = blockIdx.x * 64;

    uint32_t aoff[2], boff[2];
    frag_offsets2(warp, lane, aoff, boff);

    float c[2][4][4];
#pragma unroll
    for (int mi = 0; mi < 2; mi++)
#pragma unroll
        for (int nj = 0; nj < 4; nj++)
#pragma unroll
            for (int r = 0; r < 4; r++) c[mi][nj][r] = 0.f;

    gemm_core2(A, B, c, smemBase, tid, rowBase, colBase, aoff, boff);

    const int mW = (warp >> 1) * 32;
    const int nW = (warp & 1) * 32;
#pragma unroll
    for (int nj = 0; nj < 4; nj++) {
        const int col = colBase + nW + nj * 8 + (lane & 3) * 2;
        const float b0 = bias[col], b1 = bias[col + 1];
#pragma unroll
        for (int mi = 0; mi < 2; mi++) {
            const int row = rowBase + mW + mi * 16 + (lane >> 2);
            *(float2*)&C[(size_t)row * EE + col] =
                make_float2(c[mi][nj][0] + b0, c[mi][nj][1] + b1);
            *(float2*)&C[(size_t)(row + 8) * EE + col] =
                make_float2(c[mi][nj][2] + b0, c[mi][nj][3] + b1);
        }
    }
}

// ---------------------------------------------------------------------------
// FP16 tensor-core flash attention (unchanged): 128 q-rows/CTA, 8 warps,
// double-buffered cp.async K/V, one barrier per ktile. grid (HH, LL/128, NSEG).
// ---------------------------------------------------------------------------
#define AS      72
#define QBYTES  (128 * AS * 2)
#define KVBYTES (64 * AS * 2)
#define KOFFB(b) (QBYTES + (b) * 2 * KVBYTES)
#define VOFFB(b) (KOFFB(b) + KVBYTES)
#define SOFFB   (QBYTES + 4 * KVBYTES)

__global__ __launch_bounds__(256, 2)
void attn_h(const float* __restrict__ mask)
{
    extern __shared__ char smc[];
    __half* Qs = (__half*)smc;
    __half* Ss = (__half*)(smc + SOFFB);
    const uint32_t smemBase = (uint32_t)__cvta_generic_to_shared(smc);

    const int h   = blockIdx.x;
    const int q0  = blockIdx.y * 128;
    const int seg = blockIdx.z;
    const int tid = threadIdx.x;
    const int warp = tid >> 5;
    const int lane = tid & 31;
    const int r0 = lane >> 2;
    const int cb = (lane & 3) * 2;

    for (int i = tid; i < 128 * 8; i += 256) {
        const int r = i >> 3, c8 = (i & 7) * 8;
        *(uint4*)&Qs[r * AS + c8] =
            *(const uint4*)&g_qh[(size_t)(seg * LL + q0 + r) * EE + h * DD + c8];
    }

    const uint32_t qoff = smemBase + (uint32_t)(((warp * 16 + (lane & 15)) * AS
                                                 + ((lane >> 4) << 3)) << 1);
    const uint32_t poff = qoff + (uint32_t)SOFFB;
    uint32_t kvoff[4];
#pragma unroll
    for (int np = 0; np < 4; np++)
        kvoff[np] = (uint32_t)(((np * 16 + (lane & 7) + ((lane >> 4) << 3)) * AS
                                + (((lane >> 3) & 1) << 3)) << 1);

    const int ch0 = tid * 2;
    const __half* kbase = &g_kh[(size_t)(seg * LL) * EE + h * DD];
    const __half* vbase = &g_vth[(size_t)(h * DD) * TT + seg * LL];

    float o[8][4];
#pragma unroll
    for (int nj = 0; nj < 8; nj++)
#pragma unroll
        for (int r = 0; r < 4; r++) o[nj][r] = 0.f;
    float mrow[2] = {-INFINITY, -INFINITY};
    float lrow[2] = {0.f, 0.f};

    {
#pragma unroll
        for (int u = 0; u < 2; u++) {
            const int ch = ch0 + u;
            const int r = ch >> 3, c8 = (ch & 7) * 8;
            cp_async16(smemBase + KOFFB(0) + (uint32_t)((r * AS + c8) << 1),
                       kbase + (size_t)r * EE + c8);
            cp_async16(smemBase + VOFFB(0) + (uint32_t)((r * AS + c8) << 1),
                       vbase + (size_t)r * TT + c8);
        }
        cp_commit();
    }

    for (int kt = 0; kt < 16; kt++) {
        const int k0 = kt * 64;
        cp_wait<0>();
        __syncthreads();

        if (kt + 1 < 16) {
            const int kn = (kt + 1) * 64;
            const uint32_t kb = smemBase + KOFFB((kt + 1) & 1);
            const uint32_t vb = smemBase + VOFFB((kt + 1) & 1);
#pragma unroll
            for (int u = 0; u < 2; u++) {
                const int ch = ch0 + u;
                const int r = ch >> 3, c8 = (ch & 7) * 8;
                cp_async16(kb + (uint32_t)((r * AS + c8) << 1),
                           kbase + (size_t)(kn + r) * EE + c8);
                cp_async16(vb + (uint32_t)((r * AS + c8) << 1),
                           vbase + (size_t)r * TT + kn + c8);
            }
        }
        cp_commit();

        const uint32_t kbuf = smemBase + KOFFB(kt & 1);
        const uint32_t vbuf = smemBase + VOFFB(kt & 1);

        float s[8][4];
#pragma unroll
        for (int nj = 0; nj < 8; nj++)
#pragma unroll
            for (int r = 0; r < 4; r++) s[nj][r] = 0.f;

#pragma unroll
        for (int kd = 0; kd < 4; kd++) {
            const uint32_t ko = (uint32_t)(kd * 32);
            uint32_t a[4], b[4][4];
            ldsm4(a, qoff + ko);
#pragma unroll
            for (int np = 0; np < 4; np++) ldsm4(b[np], kbuf + kvoff[np] + ko);
#pragma unroll
            for (int nj = 0; nj < 8; nj++) {
                const int np = nj >> 1, hb = (nj & 1) << 1;
                mma16(s[nj], a, b[np][hb], b[np][hb + 1]);
            }
        }

        {
            const size_t mbase = (size_t)(seg * LL + q0 + warp * 16 + r0) * TT
                               + (size_t)(seg * LL + k0) + cb;
#pragma unroll
            for (int nj = 0; nj < 8; nj++) {
                float2 m0 = *(const float2*)&mask[mbase + nj * 8];
                float2 m1 = *(const float2*)&mask[mbase + nj * 8 + (size_t)8 * TT];
                s[nj][0] = s[nj][0] * 0.125f + m0.x;
                s[nj][1] = s[nj][1] * 0.125f + m0.y;
                s[nj][2] = s[nj][2] * 0.125f + m1.x;
                s[nj][3] = s[nj][3] * 0.125f + m1.y;
            }
        }

        float mx0 = s[0][0], mx1 = s[0][2];
#pragma unroll
        for (int nj = 0; nj < 8; nj++) {
            mx0 = fmaxf(mx0, fmaxf(s[nj][0], s[nj][1]));
            mx1 = fmaxf(mx1, fmaxf(s[nj][2], s[nj][3]));
        }
        mx0 = fmaxf(mx0, __shfl_xor_sync(0xffffffffu, mx0, 1));
        mx0 = fmaxf(mx0, __shfl_xor_sync(0xffffffffu, mx0, 2));
        mx1 = fmaxf(mx1, __shfl_xor_sync(0xffffffffu, mx1, 1));
        mx1 = fmaxf(mx1, __shfl_xor_sync(0xffffffffu, mx1, 2));

        const float mn0 = fmaxf(mrow[0], mx0);
        const float mn1 = fmaxf(mrow[1], mx1);
        const float al0 = __expf(mrow[0] - mn0);
        const float al1 = __expf(mrow[1] - mn1);
        mrow[0] = mn0; mrow[1] = mn1;

        float sum0 = 0.f, sum1 = 0.f;
#pragma unroll
        for (int nj = 0; nj < 8; nj++) {
            s[nj][0] = __expf(s[nj][0] - mn0); sum0 += s[nj][0];
            s[nj][1] = __expf(s[nj][1] - mn0); sum0 += s[nj][1];
            s[nj][2] = __expf(s[nj][2] - mn1); sum1 += s[nj][2];
            s[nj][3] = __expf(s[nj][3] - mn1); sum1 += s[nj][3];
        }
        sum0 += __shfl_xor_sync(0xffffffffu, sum0, 1);
        sum0 += __shfl_xor_sync(0xffffffffu, sum0, 2);
        sum1 += __shfl_xor_sync(0xffffffffu, sum1, 1);
        sum1 += __shfl_xor_sync(0xffffffffu, sum1, 2);
        lrow[0] = lrow[0] * al0 + sum0;
        lrow[1] = lrow[1] * al1 + sum1;

#pragma unroll
        for (int nj = 0; nj < 8; nj++) {
            o[nj][0] *= al0; o[nj][1] *= al0;
            o[nj][2] *= al1; o[nj][3] *= al1;
        }

        {
            __half* p0 = &Ss[(warp * 16 + r0) * AS + cb];
            __half* p1 = &Ss[(warp * 16 + r0 + 8) * AS + cb];
#pragma unroll
            for (int nj = 0; nj < 8; nj++) {
                *(__half2*)(p0 + nj * 8) = __floats2half2_rn(s[nj][0], s[nj][1]);
                *(__half2*)(p1 + nj * 8) = __floats2half2_rn(s[nj][2], s[nj][3]);
            }
        }
        __syncwarp();

#pragma unroll
        for (int kc = 0; kc < 4; kc++) {
            const uint32_t ko = (uint32_t)(kc * 32);
            uint32_t a[4], b[4][4];
            ldsm4(a, poff + ko);
#pragma unroll
            for (int np = 0; np < 4; np++) ldsm4(b[np], vbuf + kvoff[np] + ko);
#pragma unroll
            for (int nj = 0; nj < 8; nj++) {
                const int np = nj >> 1, hb = (nj & 1) << 1;
                mma16(o[nj], a, b[np][hb], b[np][hb + 1]);
            }
        }
    }

    {
        const float inv0 = 1.f / lrow[0];
        const float inv1 = 1.f / lrow[1];
        const size_t row0 = (size_t)(seg * LL + q0 + warp * 16 + r0);
#pragma unroll
        for (int nj = 0; nj < 8; nj++) {
            const int col = h * DD + nj * 8 + cb;
            *(__half2*)&g_oh[row0 * EE + col] =
                __floats2half2_rn(o[nj][0] * inv0, o[nj][1] * inv0);
            *(__half2*)&g_oh[(row0 + 8) * EE + col] =
                __floats2half2_rn(o[nj][2] * inv1, o[nj][3] * inv1);
        }
    }
}

// ---------------------------------------------------------------------------

extern "C" void kernel_launch(void* const* d_in, const int* in_sizes, int n_in,
                              void* d_out, int out_size)
{
    const float* hs   = (const float*)d_in[0];
    const float* mask = (const float*)d_in[2];
    const float* wq   = (const float*)d_in[3];
    const float* bq   = (const float*)d_in[4];
    const float* wk   = (const float*)d_in[5];
    const float* wv   = (const float*)d_in[6];
    const float* bv   = (const float*)d_in[7];
    const float* wo   = (const float*)d_in[8];
    const float* bo   = (const float*)d_in[9];
    float* out = (float*)d_out;

    __half *hh, *wh, *qh, *kh, *vth, *oh;
    cudaGetSymbolAddress((void**)&hh,  g_hh);
    cudaGetSymbolAddress((void**)&wh,  g_wh);
    cudaGetSymbolAddress((void**)&qh,  g_qh);
    cudaGetSymbolAddress((void**)&kh,  g_kh);
    cudaGetSymbolAddress((void**)&vth, g_vth);
    cudaGetSymbolAddress((void**)&oh,  g_oh);

    const int gsmem = NST2 * STGB2;               // 61440
    cudaFuncSetAttribute(gemm_qkv, cudaFuncAttributeMaxDynamicSharedMemorySize, gsmem);
    cudaFuncSetAttribute(gemm_out, cudaFuncAttributeMaxDynamicSharedMemorySize, gsmem);
    const int asmem = SOFFB + QBYTES;
    cudaFuncSetAttribute(attn_h, cudaFuncAttributeMaxDynamicSharedMemorySize, asmem);

    const int nConv = (TT * EE + 4 * EE * EE) / 4;
    f2h_all<<<nConv / 256, 256>>>(hs, wq, wk, wv, wo, hh, wh);

    gemm_qkv<<<dim3(EE / 64, TT / 128, 3), 256, gsmem>>>(hh, wh, bq, bv, qh, kh, vth);

    attn_h<<<dim3(HH, LL / 128, NSEG), 256, asmem>>>(mask);

    gemm_out<<<dim3(EE / 64, TT / 128), 256, gsmem>>>(oh, wh + 3 * (size_t)EE * EE, bo, out);
}